// round 7
// baseline (speedup 1.0000x reference)
#include <cuda_runtime.h>
#include <cstdint>

// Problem shape (fixed by the dataset)
#define Bv  4
#define Cv  64
#define Hv  384
#define Wv  768
#define HWv (Hv * Wv)          // 294912

// ONE batch worth of channel-contiguous accumulator: (HW, C) = 75 MB.
// Reused across batches so it stays L2-resident (L2 = 126 MB).
// Invariant: zero at kernel_launch entry (static zero-init + transpose
// kernel re-zeroes everything it reads).
__device__ __align__(256) float g_scratch[(size_t)HWv * Cv];
__device__ __align__(256) float g_wsum[HWv];

__device__ __forceinline__ void red_add_f32(float* p, float v) {
    asm volatile("red.global.add.f32 [%0], %1;" :: "l"(p), "f"(v) : "memory");
}

__device__ __forceinline__ void red_add_v4(float* p, float a, float b, float c, float d) {
    asm volatile("red.global.add.v4.f32 [%0], {%1, %2, %3, %4};"
                 :: "l"(p), "f"(a), "f"(b), "f"(c), "f"(d) : "memory");
}

// ---------------------------------------------------------------------------
// Scatter for ONE batch: one thread per source pixel.
// Streaming (__ldcs) reads so fmap doesn't evict the L2-resident scratch.
// ---------------------------------------------------------------------------
__global__ __launch_bounds__(256) void scatter_kernel(
    const float* __restrict__ fmap,    // (C, H, W) for this batch
    const float* __restrict__ flow,    // (2, H, W)
    const float* __restrict__ depth)   // (H, W)
{
    int p = blockIdx.x * 256 + threadIdx.x;           // over HWv
    int y = p / Wv;
    int x = p - y * Wv;

    float fx = __ldcs(flow + p);
    float fy = __ldcs(flow + HWv + p);
    float tx = (float)x + fx;
    float ty = (float)y + fy;

    // reference: valid = (tx>=0)&(tx<W-1)&(ty>=0)&(ty<H-1)
    if (!(tx >= 0.f && tx < (float)(Wv - 1) && ty >= 0.f && ty < (float)(Hv - 1)))
        return;

    int ix = (int)tx;   // trunc == floor for tx >= 0
    int iy = (int)ty;
    int idx = iy * Wv + ix;

    float w = __expf(-__ldcs(depth + p));

    red_add_f32(&g_wsum[idx], w);

    const float* src = fmap + p;                      // stride HWv over c
    float*       dst = g_scratch + (size_t)idx * Cv;  // contiguous over c

    #pragma unroll
    for (int c = 0; c < Cv; c += 4) {
        float v0 = __ldcs(src + (size_t)(c + 0) * HWv) * w;
        float v1 = __ldcs(src + (size_t)(c + 1) * HWv) * w;
        float v2 = __ldcs(src + (size_t)(c + 2) * HWv) * w;
        float v3 = __ldcs(src + (size_t)(c + 3) * HWv) * w;
        red_add_v4(dst + c, v0, v1, v2, v3);
    }
}

// ---------------------------------------------------------------------------
// Transpose (HW,C) -> (C,HW) via padded smem tile, fused with normalization,
// mask write, AND re-zeroing of the scratch (restores the zero invariant, so
// no memset pass is ever needed). Output written with streaming stores.
// ---------------------------------------------------------------------------
__global__ __launch_bounds__(256) void transpose_norm_zero_kernel(
    float* __restrict__ out_feat,      // (C, H, W) for this batch
    float* __restrict__ out_mask)      // (H, W)
{
    __shared__ float tile[32][Cv + 1];   // +1 pad: conflict-free column reads
    __shared__ float s_inv[32];
    __shared__ float s_msk[32];

    int tid = threadIdx.x;
    int p0  = blockIdx.x * 32;           // 32 pixels per block

    float4* src4 = reinterpret_cast<float4*>(g_scratch) + (size_t)p0 * (Cv / 4);
    const float4 z4 = make_float4(0.f, 0.f, 0.f, 0.f);

    #pragma unroll
    for (int i = 0; i < 2; i++) {
        int e   = tid + i * 256;         // 0..511
        int pix = e >> 4;                // /16
        int c4  = e & 15;
        float4 v = src4[pix * (Cv / 4) + c4];
        src4[pix * (Cv / 4) + c4] = z4;  // re-zero (L2-hit write)
        tile[pix][c4 * 4 + 0] = v.x;
        tile[pix][c4 * 4 + 1] = v.y;
        tile[pix][c4 * 4 + 2] = v.z;
        tile[pix][c4 * 4 + 3] = v.w;
    }
    if (tid < 32) {
        float w = g_wsum[p0 + tid];
        g_wsum[p0 + tid] = 0.f;          // re-zero
        s_inv[tid] = (w > 0.f) ? (1.f / w) : 1.f;
        s_msk[tid] = (w > 0.f) ? 1.f : 0.f;
    }
    __syncthreads();

    // Write: lane -> pixel (coalesced per channel), 8 channels per thread
    int lane = tid & 31;
    int cb   = tid >> 5;                 // 0..7
    float inv = s_inv[lane];
    #pragma unroll
    for (int c = cb; c < Cv; c += 8) {
        __stcs(&out_feat[(size_t)c * HWv + p0 + lane], tile[lane][c] * inv);
    }
    if (tid < 32) {
        __stcs(&out_mask[p0 + tid], s_msk[tid]);
    }
}

// ---------------------------------------------------------------------------
// Launch: per-batch serial pipeline (scatter -> transpose+rezero) so the
// 75 MB scratch stays L2-resident and is recycled between batches.
// ---------------------------------------------------------------------------
extern "C" void kernel_launch(void* const* d_in, const int* in_sizes, int n_in,
                              void* d_out, int out_size)
{
    const float* fmap  = (const float*)d_in[0];  // (B, C, H, W)
    const float* flow  = (const float*)d_in[1];  // (B, 2, H, W)
    const float* depth = (const float*)d_in[2];  // (B, 1, H, W)

    float* out_feat = (float*)d_out;                               // (B,C,H,W)
    float* out_mask = out_feat + (size_t)Bv * Cv * HWv;            // (B,1,H,W)

    for (int b = 0; b < Bv; b++) {
        scatter_kernel<<<HWv / 256, 256>>>(
            fmap  + (size_t)b * Cv * HWv,
            flow  + (size_t)b * 2 * HWv,
            depth + (size_t)b * HWv);

        transpose_norm_zero_kernel<<<HWv / 32, 256>>>(
            out_feat + (size_t)b * Cv * HWv,
            out_mask + (size_t)b * HWv);
    }
}

// round 12
// speedup vs baseline: 2.8810x; 2.8810x over previous
#include <cuda_runtime.h>
#include <cstdint>

// Problem shape (fixed by the dataset)
#define Bv  4
#define Cv  64
#define Hv  384
#define Wv  768
#define HWv (Hv * Wv)          // 294912
#define TPB 128                // scatter tile: 128 pixels/block

// Channel-contiguous accumulator: (B, HW, C). 302 MB device-global scratch.
__device__ __align__(256) float g_scratch[(size_t)Bv * HWv * Cv];
__device__ __align__(256) float g_wsum[Bv * HWv];

__device__ __forceinline__ void red_add_f32(float* p, float v) {
    asm volatile("red.global.add.f32 [%0], %1;" :: "l"(p), "f"(v) : "memory");
}

// ---------------------------------------------------------------------------
// Scatter with smem staging.
// Load phase (thread = pixel): coalesced fmap reads, premultiplied by w,
// into s_feat[C][TPB+1] (conflict-free STS: fixed c, consecutive tid).
// Atomic phase (warp = pixel): lanes cover channels {lane, lane+32} ->
// each red.f32 warp-instr is 32 consecutive floats = ONE 128B line = 1
// wavefront (vs ~32 for the scattered per-thread v4 reductions).
// ---------------------------------------------------------------------------
__global__ __launch_bounds__(TPB) void scatter_kernel(
    const float* __restrict__ fmap,    // (B, C, H, W)
    const float* __restrict__ flow,    // (B, 2, H, W)
    const float* __restrict__ depth)   // (B, 1, H, W)
{
    __shared__ float s_feat[Cv][TPB + 1];   // +1 pad: (lane+px)%32 banks, conflict-free
    __shared__ int   s_idx[TPB];

    int tid = threadIdx.x;
    int t   = blockIdx.x * TPB + tid;       // over Bv*HWv (HWv % TPB == 0: no batch straddle)
    int b   = t / HWv;
    int p   = t - b * HWv;
    int y   = p / Wv;
    int x   = p - y * Wv;

    float fx = flow[(size_t)(b * 2 + 0) * HWv + p];
    float fy = flow[(size_t)(b * 2 + 1) * HWv + p];
    float tx = (float)x + fx;
    float ty = (float)y + fy;

    // reference: valid = (tx>=0)&(tx<W-1)&(ty>=0)&(ty<H-1)
    int idx = -1;
    if (tx >= 0.f && tx < (float)(Wv - 1) && ty >= 0.f && ty < (float)(Hv - 1)) {
        int ix = (int)tx;                   // trunc == floor for tx >= 0
        int iy = (int)ty;
        idx = iy * Wv + ix;

        float w = __expf(-depth[(size_t)b * HWv + p]);
        red_add_f32(&g_wsum[(size_t)b * HWv + idx], w);

        const float* src = fmap + (size_t)b * Cv * HWv + p;   // stride HWv over c
        #pragma unroll
        for (int c = 0; c < Cv; c++) {
            s_feat[c][tid] = src[(size_t)c * HWv] * w;        // coalesced LDG, clean STS
        }
    }
    s_idx[tid] = idx;
    __syncthreads();

    int wid  = tid >> 5;
    int lane = tid & 31;
    float* base = g_scratch + (size_t)b * HWv * Cv;           // batch uniform per block

    #pragma unroll 4
    for (int j = 0; j < 32; j++) {
        int px = (wid << 5) + j;
        int ix = s_idx[px];                                   // broadcast read
        if (ix < 0) continue;
        float v0 = s_feat[lane][px];                          // conflict-free LDS
        float v1 = s_feat[lane + 32][px];
        float* d = base + (size_t)ix * Cv;                    // 256B-aligned pixel row
        red_add_f32(d + lane,      v0);                       // 128B line -> 1 wavefront
        red_add_f32(d + lane + 32, v1);                       // 128B line -> 1 wavefront
    }
}

// ---------------------------------------------------------------------------
// Transpose (B,HW,C) -> (B,C,HW) through padded smem tile, fused with
// weight normalization + mask write. (Unchanged from the 334us version.)
// ---------------------------------------------------------------------------
__global__ __launch_bounds__(256) void transpose_norm_kernel(
    float* __restrict__ out_feat,
    float* __restrict__ out_mask)
{
    __shared__ float tile[32][Cv + 1];   // +1 pad: conflict-free column reads
    __shared__ float s_inv[32];
    __shared__ float s_msk[32];

    int tid = threadIdx.x;
    int p0  = blockIdx.x * 32;           // 32 pixels per block
    int b   = blockIdx.y;

    const float4* src4 = reinterpret_cast<const float4*>(g_scratch)
                       + ((size_t)b * HWv + p0) * (Cv / 4);
    #pragma unroll
    for (int i = 0; i < 2; i++) {
        int e   = tid + i * 256;         // 0..511
        int pix = e >> 4;                // /16
        int c4  = e & 15;
        float4 v = src4[pix * (Cv / 4) + c4];
        tile[pix][c4 * 4 + 0] = v.x;
        tile[pix][c4 * 4 + 1] = v.y;
        tile[pix][c4 * 4 + 2] = v.z;
        tile[pix][c4 * 4 + 3] = v.w;
    }
    if (tid < 32) {
        float w = g_wsum[(size_t)b * HWv + p0 + tid];
        s_inv[tid] = (w > 0.f) ? (1.f / w) : 1.f;
        s_msk[tid] = (w > 0.f) ? 1.f : 0.f;
    }
    __syncthreads();

    int lane = tid & 31;
    int cb   = tid >> 5;                 // 0..7
    float inv = s_inv[lane];
    #pragma unroll
    for (int c = cb; c < Cv; c += 8) {
        out_feat[((size_t)b * Cv + c) * HWv + p0 + lane] = tile[lane][c] * inv;
    }
    if (tid < 32) {
        out_mask[(size_t)b * HWv + p0 + tid] = s_msk[tid];
    }
}

// ---------------------------------------------------------------------------
// Launch (R2 structure: full-batch kernels + memsets)
// ---------------------------------------------------------------------------
extern "C" void kernel_launch(void* const* d_in, const int* in_sizes, int n_in,
                              void* d_out, int out_size)
{
    const float* fmap  = (const float*)d_in[0];  // (B, C, H, W)
    const float* flow  = (const float*)d_in[1];  // (B, 2, H, W)
    const float* depth = (const float*)d_in[2];  // (B, 1, H, W)

    float* out_feat = (float*)d_out;                               // (B,C,H,W)
    float* out_mask = out_feat + (size_t)Bv * Cv * HWv;            // (B,1,H,W)

    void* scratch_ptr = nullptr;
    void* wsum_ptr    = nullptr;
    cudaGetSymbolAddress(&scratch_ptr, g_scratch);
    cudaGetSymbolAddress(&wsum_ptr,    g_wsum);

    cudaMemsetAsync(scratch_ptr, 0, (size_t)Bv * HWv * Cv * sizeof(float));
    cudaMemsetAsync(wsum_ptr,    0, (size_t)Bv * HWv * sizeof(float));

    scatter_kernel<<<(Bv * HWv) / TPB, TPB>>>(fmap, flow, depth);

    dim3 grid(HWv / 32, Bv);             // 9216 x 4
    transpose_norm_kernel<<<grid, 256>>>(out_feat, out_mask);
}

// round 13
// speedup vs baseline: 3.9366x; 1.3664x over previous
#include <cuda_runtime.h>
#include <cuda_fp16.h>
#include <cstdint>

// Problem shape (fixed by the dataset)
#define Bv  4
#define Cv  64
#define Hv  384
#define Wv  768
#define HWv (Hv * Wv)          // 294912
#define TPB 128                // scatter tile: 128 pixels/block

// Channel-contiguous fp16 accumulator: (B, HW, C) = 151 MB.
// One pixel row = 64 halves = exactly one 128B cache line.
__device__ __align__(256) __half g_scratch[(size_t)Bv * HWv * Cv];
__device__ __align__(256) float  g_wsum[Bv * HWv];

__device__ __forceinline__ void red_add_f32(float* p, float v) {
    asm volatile("red.global.add.f32 [%0], %1;" :: "l"(p), "f"(v) : "memory");
}

__device__ __forceinline__ void red_add_f16x2(__half2* p, unsigned v) {
    asm volatile("red.global.add.noftz.f16x2 [%0], %1;" :: "l"(p), "r"(v) : "memory");
}

// ---------------------------------------------------------------------------
// Scatter with smem staging (fp16 payload).
// Load phase (thread = pixel): coalesced f32 fmap reads, premultiply by w in
// f32, round once to half2, stage in smem.
// Atomic phase (warp = pixel): lane covers half2 slot `lane` -> the whole
// 64-channel pixel row (128B line) is ONE red.f16x2 warp-instruction.
// ---------------------------------------------------------------------------
__global__ __launch_bounds__(TPB) void scatter_kernel(
    const float* __restrict__ fmap,    // (B, C, H, W)
    const float* __restrict__ flow,    // (B, 2, H, W)
    const float* __restrict__ depth)   // (B, 1, H, W)
{
    __shared__ __half2 s_feat[Cv / 2][TPB + 1];   // 32 x 129 half2, padded
    __shared__ int     s_idx[TPB];

    int tid = threadIdx.x;
    int t   = blockIdx.x * TPB + tid;       // over Bv*HWv (HWv % TPB == 0)
    int b   = t / HWv;
    int p   = t - b * HWv;
    int y   = p / Wv;
    int x   = p - y * Wv;

    float fx = flow[(size_t)(b * 2 + 0) * HWv + p];
    float fy = flow[(size_t)(b * 2 + 1) * HWv + p];
    float tx = (float)x + fx;
    float ty = (float)y + fy;

    // reference: valid = (tx>=0)&(tx<W-1)&(ty>=0)&(ty<H-1)
    int idx = -1;
    if (tx >= 0.f && tx < (float)(Wv - 1) && ty >= 0.f && ty < (float)(Hv - 1)) {
        int ix = (int)tx;                   // trunc == floor for tx >= 0
        int iy = (int)ty;
        idx = iy * Wv + ix;

        float w = __expf(-depth[(size_t)b * HWv + p]);
        red_add_f32(&g_wsum[(size_t)b * HWv + idx], w);

        const float* src = fmap + (size_t)b * Cv * HWv + p;   // stride HWv over c
        #pragma unroll
        for (int c2 = 0; c2 < Cv / 2; c2++) {
            float v0 = src[(size_t)(2 * c2 + 0) * HWv] * w;   // coalesced LDG
            float v1 = src[(size_t)(2 * c2 + 1) * HWv] * w;
            s_feat[c2][tid] = __floats2half2_rn(v0, v1);      // single rounding
        }
    }
    s_idx[tid] = idx;
    __syncthreads();

    int wid  = tid >> 5;
    int lane = tid & 31;
    __half* base = g_scratch + (size_t)b * HWv * Cv;          // batch uniform per block

    #pragma unroll 4
    for (int j = 0; j < 32; j++) {
        int px = (wid << 5) + j;
        int ix = s_idx[px];                                   // broadcast read
        if (ix < 0) continue;
        __half2 v = s_feat[lane][px];                         // conflict-free LDS
        __half2* d = reinterpret_cast<__half2*>(base + (size_t)ix * Cv) + lane;
        red_add_f16x2(d, *reinterpret_cast<unsigned*>(&v));   // 1 line -> 1 wavefront
    }
}

// ---------------------------------------------------------------------------
// Transpose (B,HW,C) fp16 -> (B,C,HW) f32, fused with weight normalization
// + mask write. uint4 reads (one pixel row = 2 warps' worth of 16B chunks),
// padded half2 tile, conflict-free both directions.
// ---------------------------------------------------------------------------
__global__ __launch_bounds__(256) void transpose_norm_kernel(
    float* __restrict__ out_feat,
    float* __restrict__ out_mask)
{
    __shared__ __half2 tile[32][Cv / 2 + 1];   // 32 pixels x 32 half2 (+pad)
    __shared__ float   s_inv[32];
    __shared__ float   s_msk[32];

    int tid = threadIdx.x;
    int p0  = blockIdx.x * 32;           // 32 pixels per block
    int b   = blockIdx.y;

    // Load: 32 pixel rows x 128B; thread e reads one uint4 (8 halves).
    {
        int pix = tid >> 3;              // 0..31
        int q   = tid & 7;               // 0..7 (16B chunk within row)
        const uint4* row = reinterpret_cast<const uint4*>(
            g_scratch + ((size_t)b * HWv + p0 + pix) * Cv);
        uint4 v = row[q];
        tile[pix][4 * q + 0] = *reinterpret_cast<__half2*>(&v.x);
        tile[pix][4 * q + 1] = *reinterpret_cast<__half2*>(&v.y);
        tile[pix][4 * q + 2] = *reinterpret_cast<__half2*>(&v.z);
        tile[pix][4 * q + 3] = *reinterpret_cast<__half2*>(&v.w);
    }
    if (tid < 32) {
        float w = g_wsum[(size_t)b * HWv + p0 + tid];
        s_inv[tid] = (w > 0.f) ? (1.f / w) : 1.f;
        s_msk[tid] = (w > 0.f) ? 1.f : 0.f;
    }
    __syncthreads();

    // Write: lane -> pixel (coalesced per channel plane), 4 half2 per thread.
    int lane = tid & 31;
    int wb   = tid >> 5;                 // 0..7
    float inv = s_inv[lane];
    #pragma unroll
    for (int k = 0; k < 4; k++) {
        int c2 = wb + 8 * k;             // half2 slot = channels (2c2, 2c2+1)
        float2 f = __half22float2(tile[lane][c2]);
        out_feat[((size_t)b * Cv + 2 * c2 + 0) * HWv + p0 + lane] = f.x * inv;
        out_feat[((size_t)b * Cv + 2 * c2 + 1) * HWv + p0 + lane] = f.y * inv;
    }
    if (tid < 32) {
        out_mask[(size_t)b * HWv + p0 + tid] = s_msk[tid];
    }
}

// ---------------------------------------------------------------------------
// Launch
// ---------------------------------------------------------------------------
extern "C" void kernel_launch(void* const* d_in, const int* in_sizes, int n_in,
                              void* d_out, int out_size)
{
    const float* fmap  = (const float*)d_in[0];  // (B, C, H, W)
    const float* flow  = (const float*)d_in[1];  // (B, 2, H, W)
    const float* depth = (const float*)d_in[2];  // (B, 1, H, W)

    float* out_feat = (float*)d_out;                               // (B,C,H,W)
    float* out_mask = out_feat + (size_t)Bv * Cv * HWv;            // (B,1,H,W)

    void* scratch_ptr = nullptr;
    void* wsum_ptr    = nullptr;
    cudaGetSymbolAddress(&scratch_ptr, g_scratch);
    cudaGetSymbolAddress(&wsum_ptr,    g_wsum);

    cudaMemsetAsync(scratch_ptr, 0, (size_t)Bv * HWv * Cv * sizeof(__half));
    cudaMemsetAsync(wsum_ptr,    0, (size_t)Bv * HWv * sizeof(float));

    scatter_kernel<<<(Bv * HWv) / TPB, TPB>>>(fmap, flow, depth);

    dim3 grid(HWv / 32, Bv);             // 9216 x 4
    transpose_norm_kernel<<<grid, 256>>>(out_feat, out_mask);
}

// round 14
// speedup vs baseline: 4.3217x; 1.0978x over previous
#include <cuda_runtime.h>
#include <cuda_fp16.h>
#include <cstdint>

// Problem shape (fixed by the dataset)
#define Bv  4
#define Cv  64
#define Hv  384
#define Wv  768
#define HWv (Hv * Wv)          // 294912
#define TPB 128                // scatter tile: 128 pixels/block

// ONE batch of channel-contiguous fp16 accumulator: (HW, C) = 37.7 MB.
// Reused serially across batches -> stays L2-resident (L2 = 126 MB).
__device__ __align__(256) __half g_scratch[(size_t)HWv * Cv];
__device__ __align__(256) float  g_wsum[HWv];

__device__ __forceinline__ void red_add_f32(float* p, float v) {
    asm volatile("red.global.add.f32 [%0], %1;" :: "l"(p), "f"(v) : "memory");
}

__device__ __forceinline__ void red_add_f16x2(__half2* p, unsigned v) {
    asm volatile("red.global.add.noftz.f16x2 [%0], %1;" :: "l"(p), "r"(v) : "memory");
}

// ---------------------------------------------------------------------------
// Scatter for ONE batch (identical memory pattern to the 189us champion).
// __ldcs on input streams: evict-first, protects the L2-resident scratch.
// ---------------------------------------------------------------------------
__global__ __launch_bounds__(TPB) void scatter_kernel(
    const float* __restrict__ fmap,    // (C, H, W) for this batch
    const float* __restrict__ flow,    // (2, H, W)
    const float* __restrict__ depth)   // (H, W)
{
    __shared__ __half2 s_feat[Cv / 2][TPB + 1];
    __shared__ int     s_idx[TPB];

    int tid = threadIdx.x;
    int p   = blockIdx.x * TPB + tid;       // over HWv
    int y   = p / Wv;
    int x   = p - y * Wv;

    float fx = __ldcs(flow + p);
    float fy = __ldcs(flow + HWv + p);
    float tx = (float)x + fx;
    float ty = (float)y + fy;

    // reference: valid = (tx>=0)&(tx<W-1)&(ty>=0)&(ty<H-1)
    int idx = -1;
    if (tx >= 0.f && tx < (float)(Wv - 1) && ty >= 0.f && ty < (float)(Hv - 1)) {
        int ix = (int)tx;                   // trunc == floor for tx >= 0
        int iy = (int)ty;
        idx = iy * Wv + ix;

        float w = __expf(-__ldcs(depth + p));
        red_add_f32(&g_wsum[idx], w);

        const float* src = fmap + p;        // stride HWv over c
        #pragma unroll
        for (int c2 = 0; c2 < Cv / 2; c2++) {
            float v0 = __ldcs(src + (size_t)(2 * c2 + 0) * HWv) * w;
            float v1 = __ldcs(src + (size_t)(2 * c2 + 1) * HWv) * w;
            s_feat[c2][tid] = __floats2half2_rn(v0, v1);
        }
    }
    s_idx[tid] = idx;
    __syncthreads();

    int wid  = tid >> 5;
    int lane = tid & 31;

    #pragma unroll 4
    for (int j = 0; j < 32; j++) {
        int px = (wid << 5) + j;
        int ix = s_idx[px];                                   // broadcast read
        if (ix < 0) continue;
        __half2 v = s_feat[lane][px];                         // conflict-free LDS
        __half2* d = reinterpret_cast<__half2*>(g_scratch + (size_t)ix * Cv) + lane;
        red_add_f16x2(d, *reinterpret_cast<unsigned*>(&v));   // 1 line -> 1 wf, L2-hit
    }
}

// ---------------------------------------------------------------------------
// Transpose (HW,C) fp16 -> (C,HW) f32 for ONE batch, fused normalization +
// mask. 64 pixels/block => 2 uint4 loads per thread (MLP=2) to hide L2-hit
// latency. Streaming stores on outputs.
// ---------------------------------------------------------------------------
__global__ __launch_bounds__(256) void transpose_norm_kernel(
    float* __restrict__ out_feat,      // (C, H, W) for this batch
    float* __restrict__ out_mask)      // (H, W)
{
    __shared__ __half2 tile[64][Cv / 2 + 1];   // 64 px x 32 half2 (+pad) = 8.4 KB
    __shared__ float   s_inv[64];
    __shared__ float   s_msk[64];

    int tid = threadIdx.x;
    int p0  = blockIdx.x * 64;           // 64 pixels per block

    // Load: 64 rows x 8 uint4 chunks = 512 loads, 2 per thread (independent).
    #pragma unroll
    for (int i = 0; i < 2; i++) {
        int e   = tid + i * 256;         // 0..511
        int pix = e >> 3;                // 0..63
        int q   = e & 7;                 // 16B chunk in row
        const uint4* row = reinterpret_cast<const uint4*>(
            g_scratch + (size_t)(p0 + pix) * Cv);
        uint4 v = row[q];
        tile[pix][4 * q + 0] = *reinterpret_cast<__half2*>(&v.x);
        tile[pix][4 * q + 1] = *reinterpret_cast<__half2*>(&v.y);
        tile[pix][4 * q + 2] = *reinterpret_cast<__half2*>(&v.z);
        tile[pix][4 * q + 3] = *reinterpret_cast<__half2*>(&v.w);
    }
    if (tid < 64) {
        float w = g_wsum[p0 + tid];
        s_inv[tid] = (w > 0.f) ? (1.f / w) : 1.f;
        s_msk[tid] = (w > 0.f) ? 1.f : 0.f;
    }
    __syncthreads();

    // Write: px = tid&63 (64 consecutive pixels -> coalesced 256B per 2 warps),
    // 8 half2 slots per thread.
    int px = tid & 63;
    int sg = tid >> 6;                   // 0..3
    float inv = s_inv[px];
    #pragma unroll
    for (int k = 0; k < 8; k++) {
        int c2 = sg + 4 * k;             // half2 slot -> channels (2c2, 2c2+1)
        float2 f = __half22float2(tile[px][c2]);
        __stcs(&out_feat[(size_t)(2 * c2 + 0) * HWv + p0 + px], f.x * inv);
        __stcs(&out_feat[(size_t)(2 * c2 + 1) * HWv + p0 + px], f.y * inv);
    }
    if (tid < 64) {
        __stcs(&out_mask[p0 + tid], s_msk[tid]);
    }
}

// ---------------------------------------------------------------------------
// Launch: serial per-batch pipeline over one L2-resident scratch.
// ---------------------------------------------------------------------------
extern "C" void kernel_launch(void* const* d_in, const int* in_sizes, int n_in,
                              void* d_out, int out_size)
{
    const float* fmap  = (const float*)d_in[0];  // (B, C, H, W)
    const float* flow  = (const float*)d_in[1];  // (B, 2, H, W)
    const float* depth = (const float*)d_in[2];  // (B, 1, H, W)

    float* out_feat = (float*)d_out;                               // (B,C,H,W)
    float* out_mask = out_feat + (size_t)Bv * Cv * HWv;            // (B,1,H,W)

    void* scratch_ptr = nullptr;
    void* wsum_ptr    = nullptr;
    cudaGetSymbolAddress(&scratch_ptr, g_scratch);
    cudaGetSymbolAddress(&wsum_ptr,    g_wsum);

    for (int b = 0; b < Bv; b++) {
        cudaMemsetAsync(scratch_ptr, 0, (size_t)HWv * Cv * sizeof(__half));
        cudaMemsetAsync(wsum_ptr,    0, (size_t)HWv * sizeof(float));

        scatter_kernel<<<HWv / TPB, TPB>>>(
            fmap  + (size_t)b * Cv * HWv,
            flow  + (size_t)b * 2 * HWv,
            depth + (size_t)b * HWv);

        transpose_norm_kernel<<<HWv / 64, 256>>>(
            out_feat + (size_t)b * Cv * HWv,
            out_mask + (size_t)b * HWv);
    }
}